// round 2
// baseline (speedup 1.0000x reference)
#include <cuda_runtime.h>

// Problem constants
#define T_STEPS 1024
#define BATCH   128
#define FEAT    64
#define HID     256
#define KDIM    (HID + FEAT)   // 320
#define NCTA    128
#define TPB     256
#define TF      (T_STEPS * FEAT)  // 65536

// ---------------- device scratch (no allocations allowed) ----------------
__device__ float g_xT[T_STEPS * FEAT * BATCH];   // 32MB: xT[t][f][b]
__device__ float g_S[2 * HID * BATCH];           // double-buffered h, k-major: S[buf][k][b]
__device__ volatile unsigned g_flags[NCTA];
__device__ volatile unsigned g_gen;
__device__ unsigned g_done;

// packed f32x2 FMA (2 fp32 MACs per instruction -> full-rate fp32 on sm_103a)
#define FMA2(D, S, W) asm("fma.rn.f32x2 %0, %1, %2, %0;" : "+l"(D) : "l"(S), "l"(W))

// ---------------- input transpose: ts[b][t][f] -> xT[t][f][b] ----------------
__global__ void transpose_x_kernel(const float* __restrict__ ts) {
    __shared__ float tile[FEAT * 129];
    int t = blockIdx.x;
    for (int i = threadIdx.x; i < BATCH * FEAT; i += TPB) {
        int b = i >> 6, f = i & 63;
        tile[f * 129 + b] = ts[b * TF + t * FEAT + f];
    }
    __syncthreads();
    for (int i = threadIdx.x; i < BATCH * FEAT; i += TPB) {
        int f = i >> 7, b = i & 127;
        g_xT[t * (FEAT * BATCH) + f * BATCH + b] = tile[f * 129 + b];
    }
}

// ---------------- grid barrier (all 128 CTAs co-resident) ----------------
__device__ __forceinline__ void grid_barrier(unsigned expect) {
    __syncthreads();
    if (threadIdx.x == 0) {
        __threadfence();
        g_flags[blockIdx.x] = expect;
    }
    if (blockIdx.x == 0) {
        if (threadIdx.x < NCTA) {
            while (g_flags[threadIdx.x] < expect) { }
        }
        __syncthreads();
        if (threadIdx.x == 0) {
            __threadfence();
            g_gen = expect;
        }
    }
    if (threadIdx.x == 0) {
        while (g_gen < expect) { }
        __threadfence();
    }
    __syncthreads();
}

// ---------------- weight slice load into SMEM (duplicated for f32x2) ----------------
// r_local = jj*4 + gate ; r_global = gate*HID + j0 + jj
__device__ __forceinline__ void load_weights(const float* __restrict__ Whh,
                                             const float* __restrict__ Wih,
                                             const float* __restrict__ bias,
                                             float* w2, float* bias_s, int j0) {
    for (int idx = threadIdx.x; idx < KDIM * 8; idx += TPB) {
        int k = idx >> 3, r = idx & 7;
        int jj = r >> 2, gate = r & 3;
        int rg = gate * HID + j0 + jj;
        float v = (k < HID) ? Whh[rg * HID + k] : Wih[rg * FEAT + (k - HID)];
        w2[(k * 8 + r) * 2 + 0] = v;
        w2[(k * 8 + r) * 2 + 1] = v;
    }
    if (threadIdx.x < 8) {
        int r = threadIdx.x;
        bias_s[r] = bias[(r & 3) * HID + j0 + (r >> 2)];
    }
}

// ---------------- one LSTM step ----------------
template <bool OUT>
__device__ __forceinline__ void do_step(
    int t,
    const float* __restrict__ Scur, float* __restrict__ Snxt,
    const float* __restrict__ w2, const float* __restrict__ wout2,
    float* red, float* red_o, float* gates_s, float* c_s, float* osum_s,
    const float* bias_s,
    float* __restrict__ out, bool has_out, float bout_f, int j0)
{
    const int tid = threadIdx.x;
    const int ks  = tid >> 5;            // k-slice (warp id), 0..7 -> k in [ks*40, ks*40+40)
    const int b0  = (tid & 31) << 2;     // 4 consecutive batches per thread

    unsigned long long accA[8], accB[8]; // accA: b0,b0+1 ; accB: b0+2,b0+3
#pragma unroll
    for (int r = 0; r < 8; ++r) { accA[r] = 0ull; accB[r] = 0ull; }
    unsigned long long oA = 0ull, oB = 0ull;

    const int klo = ks * 40;
    const int kmidS = (klo + 40 < HID) ? (klo + 40) : HID;

    const float* sp = Scur + b0;
    // ---- h part (k < 256), also accumulates output projection when OUT ----
#pragma unroll 4
    for (int k = klo; k < kmidS; ++k) {
        ulonglong2 sv = *(const ulonglong2*)(sp + k * BATCH);
        const unsigned long long* wp = (const unsigned long long*)(w2 + k * 16);
#pragma unroll
        for (int r = 0; r < 8; ++r) {
            FMA2(accA[r], sv.x, wp[r]);
            FMA2(accB[r], sv.y, wp[r]);
        }
        if (OUT) {
            unsigned long long wo = *(const unsigned long long*)(wout2 + k * 2);
            FMA2(oA, sv.x, wo);
            FMA2(oB, sv.y, wo);
        }
    }
    // ---- x part (k >= 256) from pre-transposed input ----
    const float* xp = g_xT + t * (FEAT * BATCH) + b0;
    const int kxlo = (klo > HID) ? klo : HID;
#pragma unroll 4
    for (int k = kxlo; k < klo + 40; ++k) {
        ulonglong2 sv = *(const ulonglong2*)(xp + (k - HID) * BATCH);
        const unsigned long long* wp = (const unsigned long long*)(w2 + k * 16);
#pragma unroll
        for (int r = 0; r < 8; ++r) {
            FMA2(accA[r], sv.x, wp[r]);
            FMA2(accB[r], sv.y, wp[r]);
        }
    }

    // ---- write partials to SMEM ----
#pragma unroll
    for (int r = 0; r < 8; ++r) {
        ulonglong2 v; v.x = accA[r]; v.y = accB[r];
        *(ulonglong2*)(red + (ks * 8 + r) * BATCH + b0) = v;
    }
    if (OUT) {
        ulonglong2 v; v.x = oA; v.y = oB;
        *(ulonglong2*)(red_o + ks * BATCH + b0) = v;
    }
    __syncthreads();

    // ---- reduce 8 k-slices -> gates ----
    {
        int r  = tid >> 5;
        int b4 = (tid & 31) << 2;
        float4 s = make_float4(0.f, 0.f, 0.f, 0.f);
#pragma unroll
        for (int q = 0; q < 8; ++q) {
            float4 p = *(const float4*)(red + (q * 8 + r) * BATCH + b4);
            s.x += p.x; s.y += p.y; s.z += p.z; s.w += p.w;
        }
        float bb = bias_s[r];
        s.x += bb; s.y += bb; s.z += bb; s.w += bb;
        *(float4*)(gates_s + r * BATCH + b4) = s;
    }
    if (OUT && tid < 32) {
        int b4 = tid << 2;
        float4 s = make_float4(0.f, 0.f, 0.f, 0.f);
#pragma unroll
        for (int q = 0; q < 8; ++q) {
            float4 p = *(const float4*)(red_o + q * BATCH + b4);
            s.x += p.x; s.y += p.y; s.z += p.z; s.w += p.w;
        }
        *(float4*)(osum_s + b4) = s;
    }
    __syncthreads();

    // ---- pointwise LSTM cell update + output emit ----
    if (tid < BATCH) {
        int b = tid;
#pragma unroll
        for (int jj = 0; jj < 2; ++jj) {
            float gi = gates_s[(jj * 4 + 0) * BATCH + b];
            float gf = gates_s[(jj * 4 + 1) * BATCH + b];
            float gg = gates_s[(jj * 4 + 2) * BATCH + b];
            float go = gates_s[(jj * 4 + 3) * BATCH + b];
            float ig = 1.f / (1.f + __expf(-gi));
            float fg = 1.f / (1.f + __expf(-gf));
            float g  = tanhf(gg);
            float og = 1.f / (1.f + __expf(-go));
            float c  = fg * c_s[jj * BATCH + b] + ig * g;
            c_s[jj * BATCH + b] = c;
            Snxt[(j0 + jj) * BATCH + b] = og * tanhf(c);
        }
    } else if (OUT && has_out) {
        int b = tid - BATCH;
        out[b * TF + t * FEAT + blockIdx.x] = osum_s[b] + bout_f;
    }
}

// ---------------- persistent kernel ----------------
// SMEM layout (floats):
//   w2     [320*8*2]  = 5120   @ 0
//   wout2  [320*2]    = 640    @ 5120
//   red    [8*8*128]  = 8192   @ 5760
//   red_o  [8*128]    = 1024   @ 13952
//   gates  [8*128]    = 1024   @ 14976
//   c      [2*128]    = 256    @ 16000
//   osum   [128]      = 128    @ 16256
//   bias   [8]        = 8      @ 16384
#define SMEM_FLOATS 16392
#define SMEM_BYTES  (SMEM_FLOATS * 4)

__global__ void __launch_bounds__(TPB, 1) lstm_persistent_kernel(
    const float* __restrict__ ts,
    const float* __restrict__ Wih_e, const float* __restrict__ Whh_e, const float* __restrict__ b_e,
    const float* __restrict__ Wih_d, const float* __restrict__ Whh_d, const float* __restrict__ b_d,
    const float* __restrict__ Wout, const float* __restrict__ bout,
    float* __restrict__ out)
{
    extern __shared__ float sm[];
    float* w2      = sm;
    float* wout2   = sm + 5120;
    float* red     = sm + 5760;
    float* red_o   = sm + 13952;
    float* gates_s = sm + 14976;
    float* c_s     = sm + 16000;
    float* osum_s  = sm + 16256;
    float* bias_s  = sm + 16384;

    const int cta = blockIdx.x;
    const int tid = threadIdx.x;
    const int j0  = cta * 2;

    // encoder weights + zero init of h (S[0]) and c
    load_weights(Whh_e, Wih_e, b_e, w2, bias_s, j0);
    if (tid < BATCH) {
        g_S[(j0 + 0) * BATCH + tid] = 0.f;
        g_S[(j0 + 1) * BATCH + tid] = 0.f;
        c_s[tid]         = 0.f;
        c_s[BATCH + tid] = 0.f;
    }
    grid_barrier(1u);

    unsigned exp = 2u;
    int cur = 0;

    // ---- encoder ----
    for (int t = 0; t < T_STEPS; ++t) {
        do_step<false>(t, g_S + cur * HID * BATCH, g_S + (cur ^ 1) * HID * BATCH,
                       w2, wout2, red, red_o, gates_s, c_s, osum_s, bias_s,
                       out, false, 0.f, j0);
        grid_barrier(exp++);
        cur ^= 1;
    }

    // ---- switch to decoder weights ----
    load_weights(Whh_d, Wih_d, b_d, w2, bias_s, j0);
    const bool has_out = (cta < FEAT);
    for (int k = tid; k < KDIM; k += TPB) {
        float v = (has_out && k < HID) ? Wout[cta * HID + k] : 0.f;
        wout2[k * 2 + 0] = v;
        wout2[k * 2 + 1] = v;
    }
    float bout_f = has_out ? bout[cta] : 0.f;
    __syncthreads();

    // ---- decoder (reversed time); output emitted from PRE-update h ----
    for (int tt = 0; tt < T_STEPS; ++tt) {
        int t = T_STEPS - 1 - tt;
        do_step<true>(t, g_S + cur * HID * BATCH, g_S + (cur ^ 1) * HID * BATCH,
                      w2, wout2, red, red_o, gates_s, c_s, osum_s, bias_s,
                      out, has_out, bout_f, j0);
        grid_barrier(exp++);
        cur ^= 1;
    }

    // ---- reset barrier state for next launch (graph replays) ----
    __syncthreads();
    if (tid == 0) {
        atomicAdd(&g_done, 1u);
        if (cta == 0) {
            while (*((volatile unsigned*)&g_done) < NCTA) { }
            g_gen = 0u;
            for (int i = 0; i < NCTA; ++i) g_flags[i] = 0u;
            __threadfence();
            g_done = 0u;
        }
    }
}

// ---------------- launch ----------------
extern "C" void kernel_launch(void* const* d_in, const int* in_sizes, int n_in,
                              void* d_out, int out_size) {
    const float* ts    = (const float*)d_in[0];
    const float* Wih_e = (const float*)d_in[1];
    const float* Whh_e = (const float*)d_in[2];
    const float* b_e   = (const float*)d_in[3];
    const float* Wih_d = (const float*)d_in[4];
    const float* Whh_d = (const float*)d_in[5];
    const float* b_d   = (const float*)d_in[6];
    const float* Wout  = (const float*)d_in[7];
    const float* bout  = (const float*)d_in[8];
    float* out = (float*)d_out;

    cudaFuncSetAttribute(lstm_persistent_kernel,
                         cudaFuncAttributeMaxDynamicSharedMemorySize, SMEM_BYTES);

    transpose_x_kernel<<<T_STEPS, TPB>>>(ts);
    lstm_persistent_kernel<<<NCTA, TPB, SMEM_BYTES>>>(
        ts, Wih_e, Whh_e, b_e, Wih_d, Whh_d, b_d, Wout, bout, out);
}

// round 3
// speedup vs baseline: 1.1775x; 1.1775x over previous
#include <cuda_runtime.h>

// Problem constants
#define T_STEPS 1024
#define BATCH   128
#define FEAT    64
#define HID     256
#define KDIM    (HID + FEAT)   // 320
#define NCTA    128
#define TPB     512
#define NW      16             // warps per CTA
#define KH      16             // h-part k's per warp (16*16 = 256)
#define KX      4              // x-part k's per warp (16*4 = 64)
#define TF      (T_STEPS * FEAT)

// ---------------- device scratch ----------------
__device__ float g_xT[T_STEPS * FEAT * BATCH];   // 32MB: xT[t][f][b]
__device__ float g_S[2 * HID * BATCH];           // double-buffered h, k-major
__device__ volatile unsigned g_flags[NCTA];
__device__ unsigned g_done;

// packed f32x2 FMA (2 fp32 MACs per instr -> full-rate fp32 on sm_103a)
#define FMA2(D, S, W) asm("fma.rn.f32x2 %0, %1, %2, %0;" : "+l"(D) : "l"(S), "l"(W))

__device__ __forceinline__ float sigf(float x)  { return 1.f / (1.f + __expf(-x)); }
__device__ __forceinline__ float tanhff(float x){ return 2.f / (1.f + __expf(-2.f * x)) - 1.f; }

// ---------------- input transpose: ts[b][t][f] -> xT[t][f][b] ----------------
__global__ void transpose_x_kernel(const float* __restrict__ ts) {
    __shared__ float tile[FEAT * 129];
    int t = blockIdx.x;
    for (int i = threadIdx.x; i < BATCH * FEAT; i += 256) {
        int b = i >> 6, f = i & 63;
        tile[f * 129 + b] = ts[b * TF + t * FEAT + f];
    }
    __syncthreads();
    for (int i = threadIdx.x; i < BATCH * FEAT; i += 256) {
        int f = i >> 7, b = i & 127;
        g_xT[t * (FEAT * BATCH) + f * BATCH + b] = tile[f * 129 + b];
    }
}

// ---------------- symmetric one-hop grid barrier ----------------
__device__ __forceinline__ void bar_arrive(unsigned val) {
    __syncthreads();                      // all block work done (incl. Snxt stores)
    if (threadIdx.x == 0) {
        __threadfence();                  // release: promote block's writes to gpu scope
        g_flags[blockIdx.x] = val;
    }
}
__device__ __forceinline__ void bar_wait(unsigned val) {
    if (threadIdx.x < NCTA) {
        while (g_flags[threadIdx.x] < val) { }
    }
    __syncthreads();
    __threadfence();                      // acquire + L1D invalidate before reading S
}

// ---------------- weight slice load into SMEM (duplicated for f32x2) ----------------
__device__ __forceinline__ void load_weights(const float* __restrict__ Whh,
                                             const float* __restrict__ Wih,
                                             const float* __restrict__ bias,
                                             float* w2, float* bias_s, int j0) {
    for (int idx = threadIdx.x; idx < KDIM * 8; idx += TPB) {
        int k = idx >> 3, r = idx & 7;
        int jj = r >> 2, gate = r & 3;
        int rg = gate * HID + j0 + jj;
        float v = (k < HID) ? Whh[rg * HID + k] : Wih[rg * FEAT + (k - HID)];
        w2[(k * 8 + r) * 2 + 0] = v;
        w2[(k * 8 + r) * 2 + 1] = v;
    }
    if (threadIdx.x < 8) {
        int r = threadIdx.x;
        bias_s[r] = bias[(r & 3) * HID + j0 + (r >> 2)];
    }
}

// ---------------- accumulate x-part (off critical path) ----------------
__device__ __forceinline__ void accum_x(int t, unsigned long long* accA,
                                        unsigned long long* accB,
                                        const float* __restrict__ w2, int ks, int b0) {
    const float* xp = g_xT + t * (FEAT * BATCH) + b0;
    const int klo = HID + ks * KX;
#pragma unroll
    for (int k = klo; k < klo + KX; ++k) {
        ulonglong2 sv = *(const ulonglong2*)(xp + (k - HID) * BATCH);
        const unsigned long long* wp = (const unsigned long long*)(w2 + k * 16);
#pragma unroll
        for (int r = 0; r < 8; ++r) { FMA2(accA[r], sv.x, wp[r]); FMA2(accB[r], sv.y, wp[r]); }
    }
}

// ---------------- h-part GEMM (critical path) ----------------
template <bool OUT>
__device__ __forceinline__ void gemm_h(const float* __restrict__ Scur,
                                       const float* __restrict__ w2,
                                       const float* __restrict__ wout2,
                                       unsigned long long* accA, unsigned long long* accB,
                                       unsigned long long& oA, unsigned long long& oB,
                                       int ks, int b0) {
    const float* sp = Scur + b0;
    const int klo = ks * KH;
#pragma unroll 4
    for (int k = klo; k < klo + KH; ++k) {
        ulonglong2 sv = *(const ulonglong2*)(sp + k * BATCH);
        const unsigned long long* wp = (const unsigned long long*)(w2 + k * 16);
#pragma unroll
        for (int r = 0; r < 8; ++r) { FMA2(accA[r], sv.x, wp[r]); FMA2(accB[r], sv.y, wp[r]); }
        if (OUT) {
            unsigned long long wo = *(const unsigned long long*)(wout2 + k * 2);
            FMA2(oA, sv.x, wo); FMA2(oB, sv.y, wo);
        }
    }
}

// ---------------- SMEM layout (floats) ----------------
//  w2      5120  @ 0
//  wout2    512  @ 5120
//  red    16384  @ 5632    (16 slices * 8 rows * 128 b)
//  red_o   2048  @ 22016
//  gates   1024  @ 24064
//  c        256  @ 25088
//  osum     128  @ 25344
//  bias       8  @ 25472
#define SMEM_FLOATS 25480
#define SMEM_BYTES  (SMEM_FLOATS * 4)

__global__ void __launch_bounds__(TPB, 1) lstm_persistent_kernel(
    const float* __restrict__ Wih_e, const float* __restrict__ Whh_e, const float* __restrict__ b_e,
    const float* __restrict__ Wih_d, const float* __restrict__ Whh_d, const float* __restrict__ b_d,
    const float* __restrict__ Wout, const float* __restrict__ bout,
    float* __restrict__ out)
{
    extern __shared__ float sm[];
    float* w2      = sm;
    float* wout2   = sm + 5120;
    float* red     = sm + 5632;
    float* red_o   = sm + 22016;
    float* gates_s = sm + 24064;
    float* c_s     = sm + 25088;
    float* osum_s  = sm + 25344;
    float* bias_s  = sm + 25472;

    const int cta = blockIdx.x;
    const int tid = threadIdx.x;
    const int j0  = cta * 2;
    const int ks  = tid >> 5;           // warp id 0..15
    const int b0  = (tid & 31) << 2;    // 4 batches per thread

    load_weights(Whh_e, Wih_e, b_e, w2, bias_s, j0);
    if (tid < BATCH) {
        g_S[(j0 + 0) * BATCH + tid] = 0.f;
        g_S[(j0 + 1) * BATCH + tid] = 0.f;
        c_s[tid]         = 0.f;
        c_s[BATCH + tid] = 0.f;
    }

    unsigned long long accA[8], accB[8], oA = 0ull, oB = 0ull;

    bar_arrive(1u);
#pragma unroll
    for (int r = 0; r < 8; ++r) { accA[r] = 0ull; accB[r] = 0ull; }
    accum_x(0, accA, accB, w2, ks, b0);

    unsigned step = 1u;
    int cur = 0;

    // ================= encoder =================
    for (int t = 0; t < T_STEPS; ++t) {
        bar_wait(step);
        const float* Scur = g_S + cur * HID * BATCH;
        float*       Snxt = g_S + (cur ^ 1) * HID * BATCH;

        gemm_h<false>(Scur, w2, wout2, accA, accB, oA, oB, ks, b0);

#pragma unroll
        for (int r = 0; r < 8; ++r) {
            ulonglong2 v; v.x = accA[r]; v.y = accB[r];
            *(ulonglong2*)(red + (ks * 8 + r) * BATCH + b0) = v;
        }
        __syncthreads();

        { // gates reduce: each thread does (row r, 2 batches)
            int r  = tid >> 6;
            int b2 = (tid & 63) << 1;
            float2 s = make_float2(0.f, 0.f);
#pragma unroll
            for (int q = 0; q < NW; ++q) {
                float2 p = *(const float2*)(red + (q * 8 + r) * BATCH + b2);
                s.x += p.x; s.y += p.y;
            }
            float bb = bias_s[r];
            s.x += bb; s.y += bb;
            *(float2*)(gates_s + r * BATCH + b2) = s;
        }
        __syncthreads();

        if (tid < 256) { // pointwise
            int jj = tid >> 7, b = tid & 127;
            float gi = gates_s[(jj * 4 + 0) * BATCH + b];
            float gf = gates_s[(jj * 4 + 1) * BATCH + b];
            float gg = gates_s[(jj * 4 + 2) * BATCH + b];
            float go = gates_s[(jj * 4 + 3) * BATCH + b];
            float c  = sigf(gf) * c_s[jj * BATCH + b] + sigf(gi) * tanhff(gg);
            c_s[jj * BATCH + b] = c;
            Snxt[(j0 + jj) * BATCH + b] = sigf(go) * tanhff(c);
        }

        ++step;
        bar_arrive(step);
        cur ^= 1;

        if (t < T_STEPS - 1) { // prefetch-accumulate x of next step (off critical path)
#pragma unroll
            for (int r = 0; r < 8; ++r) { accA[r] = 0ull; accB[r] = 0ull; }
            accum_x(t + 1, accA, accB, w2, ks, b0);
        }
    }

    // ================= switch to decoder weights =================
    load_weights(Whh_d, Wih_d, b_d, w2, bias_s, j0);
    const bool has_out = (cta < FEAT);
    for (int k = tid; k < HID; k += TPB) {
        float v = has_out ? Wout[cta * HID + k] : 0.f;
        wout2[k * 2 + 0] = v;
        wout2[k * 2 + 1] = v;
    }
    float bout_f = has_out ? bout[cta] : 0.f;
    __syncthreads();

#pragma unroll
    for (int r = 0; r < 8; ++r) { accA[r] = 0ull; accB[r] = 0ull; }
    accum_x(T_STEPS - 1, accA, accB, w2, ks, b0);
    oA = 0ull; oB = 0ull;

    // ================= decoder (reversed time) =================
    for (int tt = 0; tt < T_STEPS; ++tt) {
        int t = T_STEPS - 1 - tt;
        bar_wait(step);
        const float* Scur = g_S + cur * HID * BATCH;
        float*       Snxt = g_S + (cur ^ 1) * HID * BATCH;

        gemm_h<true>(Scur, w2, wout2, accA, accB, oA, oB, ks, b0);

#pragma unroll
        for (int r = 0; r < 8; ++r) {
            ulonglong2 v; v.x = accA[r]; v.y = accB[r];
            *(ulonglong2*)(red + (ks * 8 + r) * BATCH + b0) = v;
        }
        { ulonglong2 v; v.x = oA; v.y = oB;
          *(ulonglong2*)(red_o + ks * BATCH + b0) = v; }
        __syncthreads();

        {
            int r  = tid >> 6;
            int b2 = (tid & 63) << 1;
            float2 s = make_float2(0.f, 0.f);
#pragma unroll
            for (int q = 0; q < NW; ++q) {
                float2 p = *(const float2*)(red + (q * 8 + r) * BATCH + b2);
                s.x += p.x; s.y += p.y;
            }
            float bb = bias_s[r];
            s.x += bb; s.y += bb;
            *(float2*)(gates_s + r * BATCH + b2) = s;
        }
        __syncthreads();

        if (tid < 256) {
            int jj = tid >> 7, b = tid & 127;
            float gi = gates_s[(jj * 4 + 0) * BATCH + b];
            float gf = gates_s[(jj * 4 + 1) * BATCH + b];
            float gg = gates_s[(jj * 4 + 2) * BATCH + b];
            float go = gates_s[(jj * 4 + 3) * BATCH + b];
            float c  = sigf(gf) * c_s[jj * BATCH + b] + sigf(gi) * tanhff(gg);
            c_s[jj * BATCH + b] = c;
            Snxt[(j0 + jj) * BATCH + b] = sigf(go) * tanhff(c);
        }

        ++step;
        bar_arrive(step);
        cur ^= 1;

        // ---- epilogue off critical path: output projection emit ----
        if (tid < 64) {
            int b2 = tid << 1;
            float2 s = make_float2(0.f, 0.f);
#pragma unroll
            for (int q = 0; q < NW; ++q) {
                float2 p = *(const float2*)(red_o + q * BATCH + b2);
                s.x += p.x; s.y += p.y;
            }
            *(float2*)(osum_s + b2) = s;
        }
        __syncthreads();
        if (has_out && tid < BATCH) {
            out[tid * TF + t * FEAT + cta] = osum_s[tid] + bout_f;
        }

        if (tt < T_STEPS - 1) {
#pragma unroll
            for (int r = 0; r < 8; ++r) { accA[r] = 0ull; accB[r] = 0ull; }
            accum_x(t - 1, accA, accB, w2, ks, b0);
            oA = 0ull; oB = 0ull;
        }
    }

    // ---- reset barrier state for graph replays ----
    __syncthreads();
    if (tid == 0) {
        atomicAdd(&g_done, 1u);
        if (cta == 0) {
            while (*((volatile unsigned*)&g_done) < NCTA) { }
            for (int i = 0; i < NCTA; ++i) g_flags[i] = 0u;
            __threadfence();
            g_done = 0u;
        }
    }
}

// ---------------- launch ----------------
extern "C" void kernel_launch(void* const* d_in, const int* in_sizes, int n_in,
                              void* d_out, int out_size) {
    const float* ts    = (const float*)d_in[0];
    const float* Wih_e = (const float*)d_in[1];
    const float* Whh_e = (const float*)d_in[2];
    const float* b_e   = (const float*)d_in[3];
    const float* Wih_d = (const float*)d_in[4];
    const float* Whh_d = (const float*)d_in[5];
    const float* b_d   = (const float*)d_in[6];
    const float* Wout  = (const float*)d_in[7];
    const float* bout  = (const float*)d_in[8];
    float* out = (float*)d_out;

    cudaFuncSetAttribute(lstm_persistent_kernel,
                         cudaFuncAttributeMaxDynamicSharedMemorySize, SMEM_BYTES);

    transpose_x_kernel<<<T_STEPS, 256>>>(ts);
    lstm_persistent_kernel<<<NCTA, TPB, SMEM_BYTES>>>(
        Wih_e, Whh_e, b_e, Wih_d, Whh_d, b_d, Wout, bout, out);
}

// round 4
// speedup vs baseline: 1.1907x; 1.0112x over previous
#include <cuda_runtime.h>

// Problem constants
#define T_STEPS 1024
#define BATCH   128
#define FEAT    64
#define HID     256
#define KDIM    (HID + FEAT)   // 320
#define NCTA    128
#define TPB     512
#define NW      16             // warps per CTA
#define KH      16             // h-part k's per warp
#define KX      4              // x-part k's per warp
#define TF      (T_STEPS * FEAT)

// ---------------- device scratch ----------------
__device__ float g_xT[T_STEPS * FEAT * BATCH];   // 32MB: xT[t][f][b]
__device__ float g_S[2 * HID * BATCH];           // double-buffered h, k-major
__device__ volatile unsigned g_flags[NCTA];
__device__ unsigned g_done;

// packed f32x2 FMA (2 fp32 MACs per instr)
#define FMA2(D, S, W) asm("fma.rn.f32x2 %0, %1, %2, %0;" : "+l"(D) : "l"(S), "l"(W))

__device__ __forceinline__ ulonglong2 ldcg128(const float* p) {
    ulonglong2 v;
    asm volatile("ld.global.cg.v2.u64 {%0,%1}, [%2];"
                 : "=l"(v.x), "=l"(v.y) : "l"(p));
    return v;
}

__device__ __forceinline__ float sigf(float x)  { return 1.f / (1.f + __expf(-x)); }
__device__ __forceinline__ float tanhff(float x){ return 2.f / (1.f + __expf(-2.f * x)) - 1.f; }

// ---------------- input transpose: ts[b][t][f] -> xT[t][f][b] ----------------
__global__ void transpose_x_kernel(const float* __restrict__ ts) {
    __shared__ float tile[FEAT * 129];
    int t = blockIdx.x;
    for (int i = threadIdx.x; i < BATCH * FEAT; i += 256) {
        int b = i >> 6, f = i & 63;
        tile[f * 129 + b] = ts[b * TF + t * FEAT + f];
    }
    __syncthreads();
    for (int i = threadIdx.x; i < BATCH * FEAT; i += 256) {
        int f = i >> 7, b = i & 127;
        g_xT[t * (FEAT * BATCH) + f * BATCH + b] = tile[f * 129 + b];
    }
}

// ---------------- symmetric one-hop grid barrier ----------------
__device__ __forceinline__ void bar_arrive(unsigned val) {
    __syncthreads();
    if (threadIdx.x == 0) {
        __threadfence();                  // release
        g_flags[blockIdx.x] = val;
    }
}
__device__ __forceinline__ void bar_wait(unsigned val) {
    if (threadIdx.x < NCTA) {
        while (g_flags[threadIdx.x] < val) { }
    }
    __syncthreads();
    __threadfence();                      // acquire ordering before reading S
}

// ---------------- weight slice load into SMEM (duplicated for f32x2) ----------------
__device__ __forceinline__ void load_weights(const float* __restrict__ Whh,
                                             const float* __restrict__ Wih,
                                             const float* __restrict__ bias,
                                             float* w2, float* bias_s, int j0) {
    for (int idx = threadIdx.x; idx < KDIM * 8; idx += TPB) {
        int k = idx >> 3, r = idx & 7;
        int jj = r >> 2, gate = r & 3;
        int rg = gate * HID + j0 + jj;
        float v = (k < HID) ? Whh[rg * HID + k] : Wih[rg * FEAT + (k - HID)];
        w2[(k * 8 + r) * 2 + 0] = v;
        w2[(k * 8 + r) * 2 + 1] = v;
    }
    if (threadIdx.x < 8) {
        int r = threadIdx.x;
        bias_s[r] = bias[(r & 3) * HID + j0 + (r >> 2)];
    }
}

// ---------------- accumulate x-part (off critical path), prefetched ----------------
__device__ __forceinline__ void accum_x(int t, unsigned long long* accA,
                                        unsigned long long* accB,
                                        const float* __restrict__ w2, int ks, int b0) {
    const float* xp = g_xT + t * (FEAT * BATCH) + b0;
    const int klo = HID + ks * KX;
    ulonglong2 sv[KX];
#pragma unroll
    for (int i = 0; i < KX; ++i) sv[i] = ldcg128(xp + (klo + i - HID) * BATCH);
#pragma unroll
    for (int i = 0; i < KX; ++i) {
        const unsigned long long* wp = (const unsigned long long*)(w2 + (klo + i) * 16);
#pragma unroll
        for (int r = 0; r < 8; ++r) { FMA2(accA[r], sv[i].x, wp[r]); FMA2(accB[r], sv[i].y, wp[r]); }
    }
}

// ---------------- h-part GEMM (critical path), 8-deep pipelined loads ----------------
template <bool OUT>
__device__ __forceinline__ void gemm_h(const float* __restrict__ Scur,
                                       const float* __restrict__ w2,
                                       const float* __restrict__ wout2,
                                       unsigned long long* accA, unsigned long long* accB,
                                       unsigned long long& oA, unsigned long long& oB,
                                       int klo, int b0) {
    const float* sp = Scur + b0;
    ulonglong2 sv[8];
#pragma unroll
    for (int i = 0; i < 8; ++i) sv[i] = ldcg128(sp + (klo + i) * BATCH);
#pragma unroll
    for (int i = 0; i < 8; ++i) {
        ulonglong2 cur = sv[i];
        sv[i] = ldcg128(sp + (klo + 8 + i) * BATCH);   // prefetch second half
        const unsigned long long* wp = (const unsigned long long*)(w2 + (klo + i) * 16);
#pragma unroll
        for (int r = 0; r < 8; ++r) { FMA2(accA[r], cur.x, wp[r]); FMA2(accB[r], cur.y, wp[r]); }
        if (OUT) {
            unsigned long long wo = *(const unsigned long long*)(wout2 + (klo + i) * 2);
            FMA2(oA, cur.x, wo); FMA2(oB, cur.y, wo);
        }
    }
#pragma unroll
    for (int i = 0; i < 8; ++i) {
        const unsigned long long* wp = (const unsigned long long*)(w2 + (klo + 8 + i) * 16);
#pragma unroll
        for (int r = 0; r < 8; ++r) { FMA2(accA[r], sv[i].x, wp[r]); FMA2(accB[r], sv[i].y, wp[r]); }
        if (OUT) {
            unsigned long long wo = *(const unsigned long long*)(wout2 + (klo + 8 + i) * 2);
            FMA2(oA, sv[i].x, wo); FMA2(oB, sv[i].y, wo);
        }
    }
}

// ---------------- SMEM layout (floats) ----------------
#define SMEM_FLOATS 25480
#define SMEM_BYTES  (SMEM_FLOATS * 4)

__global__ void __launch_bounds__(TPB, 1) lstm_persistent_kernel(
    const float* __restrict__ Wih_e, const float* __restrict__ Whh_e, const float* __restrict__ b_e,
    const float* __restrict__ Wih_d, const float* __restrict__ Whh_d, const float* __restrict__ b_d,
    const float* __restrict__ Wout, const float* __restrict__ bout,
    float* __restrict__ out)
{
    extern __shared__ float sm[];
    float* w2      = sm;            // 5120
    float* wout2   = sm + 5120;     // 512
    float* red     = sm + 5632;     // 16384
    float* red_o   = sm + 22016;    // 2048
    float* gates_s = sm + 24064;    // 1024
    float* c_s     = sm + 25088;    // 256
    float* osum_s  = sm + 25344;    // 128
    float* bias_s  = sm + 25472;    // 8

    const int cta = blockIdx.x;
    const int tid = threadIdx.x;
    const int j0  = cta * 2;
    const int ks  = tid >> 5;                      // warp id 0..15
    const int ksr = (ks + cta) & 15;               // rotated k-slice (spread L2 bursts)
    const int klo = ksr * KH;
    const int b0  = (tid & 31) << 2;               // 4 batches per thread

    load_weights(Whh_e, Wih_e, b_e, w2, bias_s, j0);
    if (tid < BATCH) {
        g_S[(j0 + 0) * BATCH + tid] = 0.f;
        g_S[(j0 + 1) * BATCH + tid] = 0.f;
        c_s[tid]         = 0.f;
        c_s[BATCH + tid] = 0.f;
    }

    unsigned long long accA[8], accB[8], oA = 0ull, oB = 0ull;

    bar_arrive(1u);
#pragma unroll
    for (int r = 0; r < 8; ++r) { accA[r] = 0ull; accB[r] = 0ull; }
    accum_x(0, accA, accB, w2, ks, b0);

    unsigned step = 1u;
    int cur = 0;

    // ================= encoder =================
    for (int t = 0; t < T_STEPS; ++t) {
        bar_wait(step);
        const float* Scur = g_S + cur * HID * BATCH;
        float*       Snxt = g_S + (cur ^ 1) * HID * BATCH;

        gemm_h<false>(Scur, w2, wout2, accA, accB, oA, oB, klo, b0);

#pragma unroll
        for (int r = 0; r < 8; ++r) {
            ulonglong2 v; v.x = accA[r]; v.y = accB[r];
            *(ulonglong2*)(red + (ks * 8 + r) * BATCH + b0) = v;
        }
        __syncthreads();

        { // gates reduce
            int r  = tid >> 6;
            int b2 = (tid & 63) << 1;
            float2 s = make_float2(0.f, 0.f);
#pragma unroll
            for (int q = 0; q < NW; ++q) {
                float2 p = *(const float2*)(red + (q * 8 + r) * BATCH + b2);
                s.x += p.x; s.y += p.y;
            }
            float bb = bias_s[r];
            s.x += bb; s.y += bb;
            *(float2*)(gates_s + r * BATCH + b2) = s;
        }
        __syncthreads();

        if (tid < 256) { // pointwise
            int jj = tid >> 7, b = tid & 127;
            float gi = gates_s[(jj * 4 + 0) * BATCH + b];
            float gf = gates_s[(jj * 4 + 1) * BATCH + b];
            float gg = gates_s[(jj * 4 + 2) * BATCH + b];
            float go = gates_s[(jj * 4 + 3) * BATCH + b];
            float c  = sigf(gf) * c_s[jj * BATCH + b] + sigf(gi) * tanhff(gg);
            c_s[jj * BATCH + b] = c;
            Snxt[(j0 + jj) * BATCH + b] = sigf(go) * tanhff(c);
        }

        ++step;
        bar_arrive(step);
        cur ^= 1;

        if (t < T_STEPS - 1) {
#pragma unroll
            for (int r = 0; r < 8; ++r) { accA[r] = 0ull; accB[r] = 0ull; }
            accum_x(t + 1, accA, accB, w2, ks, b0);
        }
    }

    // ================= switch to decoder weights =================
    load_weights(Whh_d, Wih_d, b_d, w2, bias_s, j0);
    const bool has_out = (cta < FEAT);
    for (int k = tid; k < HID; k += TPB) {
        float v = has_out ? Wout[cta * HID + k] : 0.f;
        wout2[k * 2 + 0] = v;
        wout2[k * 2 + 1] = v;
    }
    float bout_f = has_out ? bout[cta] : 0.f;
    __syncthreads();

#pragma unroll
    for (int r = 0; r < 8; ++r) { accA[r] = 0ull; accB[r] = 0ull; }
    accum_x(T_STEPS - 1, accA, accB, w2, ks, b0);
    oA = 0ull; oB = 0ull;

    // ================= decoder (reversed time) =================
    for (int tt = 0; tt < T_STEPS; ++tt) {
        int t = T_STEPS - 1 - tt;
        bar_wait(step);
        const float* Scur = g_S + cur * HID * BATCH;
        float*       Snxt = g_S + (cur ^ 1) * HID * BATCH;

        gemm_h<true>(Scur, w2, wout2, accA, accB, oA, oB, klo, b0);

#pragma unroll
        for (int r = 0; r < 8; ++r) {
            ulonglong2 v; v.x = accA[r]; v.y = accB[r];
            *(ulonglong2*)(red + (ks * 8 + r) * BATCH + b0) = v;
        }
        { ulonglong2 v; v.x = oA; v.y = oB;
          *(ulonglong2*)(red_o + ks * BATCH + b0) = v; }
        __syncthreads();

        {
            int r  = tid >> 6;
            int b2 = (tid & 63) << 1;
            float2 s = make_float2(0.f, 0.f);
#pragma unroll
            for (int q = 0; q < NW; ++q) {
                float2 p = *(const float2*)(red + (q * 8 + r) * BATCH + b2);
                s.x += p.x; s.y += p.y;
            }
            float bb = bias_s[r];
            s.x += bb; s.y += bb;
            *(float2*)(gates_s + r * BATCH + b2) = s;
        }
        __syncthreads();

        if (tid < 256) {
            int jj = tid >> 7, b = tid & 127;
            float gi = gates_s[(jj * 4 + 0) * BATCH + b];
            float gf = gates_s[(jj * 4 + 1) * BATCH + b];
            float gg = gates_s[(jj * 4 + 2) * BATCH + b];
            float go = gates_s[(jj * 4 + 3) * BATCH + b];
            float c  = sigf(gf) * c_s[jj * BATCH + b] + sigf(gi) * tanhff(gg);
            c_s[jj * BATCH + b] = c;
            Snxt[(j0 + jj) * BATCH + b] = sigf(go) * tanhff(c);
        }

        ++step;
        bar_arrive(step);
        cur ^= 1;

        // ---- epilogue off critical path: output projection emit ----
        if (tid < 64) {
            int b2 = tid << 1;
            float2 s = make_float2(0.f, 0.f);
#pragma unroll
            for (int q = 0; q < NW; ++q) {
                float2 p = *(const float2*)(red_o + q * BATCH + b2);
                s.x += p.x; s.y += p.y;
            }
            *(float2*)(osum_s + b2) = s;
        }
        __syncthreads();
        if (has_out && tid < BATCH) {
            out[tid * TF + t * FEAT + cta] = osum_s[tid] + bout_f;
        }

        if (tt < T_STEPS - 1) {
#pragma unroll
            for (int r = 0; r < 8; ++r) { accA[r] = 0ull; accB[r] = 0ull; }
            accum_x(t - 1, accA, accB, w2, ks, b0);
            oA = 0ull; oB = 0ull;
        }
    }

    // ---- reset barrier state for graph replays ----
    __syncthreads();
    if (tid == 0) {
        atomicAdd(&g_done, 1u);
        if (cta == 0) {
            while (*((volatile unsigned*)&g_done) < NCTA) { }
            for (int i = 0; i < NCTA; ++i) g_flags[i] = 0u;
            __threadfence();
            g_done = 0u;
        }
    }
}

// ---------------- launch ----------------
extern "C" void kernel_launch(void* const* d_in, const int* in_sizes, int n_in,
                              void* d_out, int out_size) {
    const float* ts    = (const float*)d_in[0];
    const float* Wih_e = (const float*)d_in[1];
    const float* Whh_e = (const float*)d_in[2];
    const float* b_e   = (const float*)d_in[3];
    const float* Wih_d = (const float*)d_in[4];
    const float* Whh_d = (const float*)d_in[5];
    const float* b_d   = (const float*)d_in[6];
    const float* Wout  = (const float*)d_in[7];
    const float* bout  = (const float*)d_in[8];
    float* out = (float*)d_out;

    cudaFuncSetAttribute(lstm_persistent_kernel,
                         cudaFuncAttributeMaxDynamicSharedMemorySize, SMEM_BYTES);

    transpose_x_kernel<<<T_STEPS, 256>>>(ts);
    lstm_persistent_kernel<<<NCTA, TPB, SMEM_BYTES>>>(
        Wih_e, Whh_e, b_e, Wih_d, Whh_d, b_d, Wout, bout, out);
}